// round 14
// baseline (speedup 1.0000x reference)
#include <cuda_runtime.h>
#include <math.h>
#include <stdint.h>

// Problem constants: B=32, T=1024, D=256, H=256
#define BB 32
#define TT 1024
#define DD 256
#define HH 256
#define GRID 148
#define NTHREADS 1024
#define TILE_ROWS 32
#define TILE_BYTES (TILE_ROWS * DD * 4)      // 32768
#define TILES_PER_BATCH (TT / TILE_ROWS)     // 32
#define NBUF 6                                // phase-1 load ring (slots 0..5)
#define NL 4                                  // phase-3 load slots 0..3
#define NS 2                                  // phase-3 store slots 4..5
#define DYN_SMEM (NBUF * TILE_BYTES)          // 196608

// Scratch (device globals — no allocation allowed; zero-init at module load)
__device__ __align__(16) float g_c[BB * DD];       // atomic c accumulator (re-zeroed each launch in phase 2b)
__device__ __align__(16) float g_h[2 * BB * HH];   // hidden exchange
__device__ __align__(16) float g_W[BB * DD];
__device__ __align__(16) float g_bias[BB * DD];
__device__ unsigned g_ticket = 0;            // barrier tickets (monotonic)
__device__ volatile unsigned g_gen = 0;      // barrier generation (monotonic)

// ---------------------------------------------------------------------------
// PTX helpers
// ---------------------------------------------------------------------------
__device__ __forceinline__ unsigned smem_u32(const void* p) {
    return (unsigned)__cvta_generic_to_shared(p);
}
__device__ __forceinline__ void mbar_init(unsigned a, unsigned cnt) {
    asm volatile("mbarrier.init.shared.b64 [%0], %1;" :: "r"(a), "r"(cnt) : "memory");
}
__device__ __forceinline__ void mbar_expect_tx(unsigned a, unsigned bytes) {
    asm volatile("mbarrier.arrive.expect_tx.shared.b64 _, [%0], %1;"
                 :: "r"(a), "r"(bytes) : "memory");
}
__device__ __forceinline__ void mbar_wait(unsigned a, int phase) {
    asm volatile(
        "{\n\t.reg .pred P;\n\t"
        "W_%=:\n\t"
        "mbarrier.try_wait.parity.acquire.cta.shared::cta.b64 P, [%0], %1, 0x989680;\n\t"
        "@P bra D_%=;\n\t"
        "bra W_%=;\n\t"
        "D_%=:\n\t}"
        :: "r"(a), "r"((unsigned)phase) : "memory");
}
__device__ __forceinline__ void bulk_load(unsigned dst_smem, const void* src_gmem,
                                          unsigned bytes, unsigned mbar) {
    asm volatile(
        "cp.async.bulk.shared::cluster.global.mbarrier::complete_tx::bytes "
        "[%0], [%1], %2, [%3];"
        :: "r"(dst_smem), "l"(src_gmem), "r"(bytes), "r"(mbar) : "memory");
}
__device__ __forceinline__ void bulk_store(void* dst_gmem, unsigned src_smem,
                                           unsigned bytes) {
    asm volatile("cp.async.bulk.global.shared::cta.bulk_group [%0], [%1], %2;"
                 :: "l"(dst_gmem), "r"(src_smem), "r"(bytes) : "memory");
}
__device__ __forceinline__ void bulk_commit()      { asm volatile("cp.async.bulk.commit_group;" ::: "memory"); }
__device__ __forceinline__ void bulk_wait_group1() { asm volatile("cp.async.bulk.wait_group 1;" ::: "memory"); }
__device__ __forceinline__ void bulk_wait_group0() { asm volatile("cp.async.bulk.wait_group 0;" ::: "memory"); }
__device__ __forceinline__ void fence_proxy_async_shared() {
    asm volatile("fence.proxy.async.shared::cta;" ::: "memory");
}

// ---------------------------------------------------------------------------
// Grid barrier (proven R7/R10): 148 arrivals, plain-load spin, never resets.
// Exactly 3 barriers per launch in this kernel.
// ---------------------------------------------------------------------------
__device__ __forceinline__ void grid_barrier() {
    __syncthreads();
    if (threadIdx.x == 0) {
        __threadfence();
        unsigned gv = g_gen;
        unsigned t = atomicAdd(&g_ticket, 1u);
        if ((t % GRID) == GRID - 1u) {
            __threadfence();
            g_gen = gv + 1u;
        } else {
            while (g_gen == gv) { __nanosleep(32); }
        }
        __threadfence();
    }
    __syncthreads();
}

__device__ __forceinline__ float gelu_exact(float v) {
    return 0.5f * v * (1.0f + erff(v * 0.70710678118654752f));
}

extern __shared__ __align__(128) char dynsmem[];

// ---------------------------------------------------------------------------
// Persistent kernel: TMA reduce(+atomic c) -> L1 -> L2 (weight-stationary) -> apply
// ---------------------------------------------------------------------------
__global__ __launch_bounds__(NTHREADS, 1) void fused_kernel(
        const float* __restrict__ x,
        const int* __restrict__ len,
        const float* __restrict__ w1w, const float* __restrict__ w1b,
        const float* __restrict__ w2w, const float* __restrict__ w2b,
        const float* __restrict__ q1w, const float* __restrict__ q1b,
        const float* __restrict__ q2w, const float* __restrict__ q2b,
        float* __restrict__ out) {
    __shared__ __align__(16) float w_sh[4 * 256];    // 4 weight rows (4 KB)
    __shared__ __align__(16) float il_sh[BB];        // 1/len per batch
    __shared__ __align__(8) unsigned long long mbar_s[NBUF];

    const int tid = threadIdx.x;
    const int d4  = tid & 63;
    const int r2  = tid >> 6;        // rows r2 and r2+16 of a tile
    const char* xb = (const char*)x;
    char*       ob = (char*)out;

    // Per-batch slab (R10): CTA -> one batch, contiguous tiles (6-8).
    const int b   = (blockIdx.x * BB) / GRID;
    const int lo  = (b * GRID + BB - 1) / BB;
    const int hi  = ((b + 1) * GRID + BB - 1) / BB;
    const int idx = blockIdx.x - lo;
    const int n   = hi - lo;
    const int t0  = b * TILES_PER_BATCH + (idx * TILES_PER_BATCH) / n;
    const int t1  = b * TILES_PER_BATCH + ((idx + 1) * TILES_PER_BATCH) / n;
    const int nt  = t1 - t0;

    unsigned mb[NBUF], bufa[NBUF];
#pragma unroll
    for (int k = 0; k < NBUF; k++) {
        mb[k]   = smem_u32(&mbar_s[k]);
        bufa[k] = smem_u32(dynsmem) + k * TILE_BYTES;
    }
    if (tid == 0) {
#pragma unroll
        for (int k = 0; k < NBUF; k++) mbar_init(mb[k], 1);
    }
    __syncthreads();
    int ph[NBUF] = {0, 0, 0, 0, 0, 0};
    float4* const bufs = (float4*)dynsmem;
    float* const cache = (float*)(dynsmem + 5 * TILE_BYTES);  // buf5: MLP cache (32 KB)

    // ---------- Phase 1: reduce via NBUF-deep TMA ring (R10 verbatim) ----------
    {
        if (tid == 0) {
            int pre = nt < NBUF ? nt : NBUF;
            for (int j = 0; j < pre; j++) {
                mbar_expect_tx(mb[j], TILE_BYTES);
                bulk_load(bufa[j], xb + (size_t)(t0 + j) * TILE_BYTES, TILE_BYTES, mb[j]);
            }
        }
        float4 acc0 = make_float4(0.f, 0.f, 0.f, 0.f);
        float4 acc1 = make_float4(0.f, 0.f, 0.f, 0.f);
        for (int i = 0; i < nt; i++) {
            int s = i % NBUF;
            mbar_wait(mb[s], ph[s]); ph[s] ^= 1;
            float4 v0 = bufs[s * 2048 + r2 * 64 + d4];
            float4 v1 = bufs[s * 2048 + (r2 + 16) * 64 + d4];
            acc0.x += v0.x; acc0.y += v0.y; acc0.z += v0.z; acc0.w += v0.w;
            acc1.x += v1.x; acc1.y += v1.y; acc1.z += v1.z; acc1.w += v1.w;
            __syncthreads();
            if (i + NBUF < nt && tid == 0) {
                mbar_expect_tx(mb[s], TILE_BYTES);
                bulk_load(bufa[s], xb + (size_t)(t0 + i + NBUF) * TILE_BYTES, TILE_BYTES, mb[s]);
            }
        }
        // flush: stage 16x64 float4 in buffer-0 region, reduce, atomicAdd to g_c
        acc0.x += acc1.x; acc0.y += acc1.y; acc0.z += acc1.z; acc0.w += acc1.w;
        bufs[r2 * 64 + d4] = acc0;
        __syncthreads();
        if (tid < 256) {
            // column tid of the 256-wide staged matrix: sum 16 rows, scalar view
            float s = 0.0f;
            const float* st = (const float*)dynsmem;
#pragma unroll
            for (int r = 0; r < 16; r++) s += st[r * 256 + tid];
            atomicAdd(&g_c[b * DD + tid], s);
        }
        __syncthreads();
        // phase-3 prefetch into slots 0..3 (buf5 reserved for MLP cache)
        if (tid == 0) {
            int pre = nt < NL ? nt : NL;
            for (int j = 0; j < pre; j++) {
                mbar_expect_tx(mb[j], TILE_BYTES);
                bulk_load(bufa[j], xb + (size_t)(t0 + j) * TILE_BYTES, TILE_BYTES, mb[j]);
            }
        }
    }
    grid_barrier();   // #1: g_c complete

    // ---------- Phase 2a: layer 1, weight-stationary (CTAs 0..127) ----------
    // CTA j owns 4 (branch, hidden) rows; computes them for ALL 32 batches.
    const bool worker = (blockIdx.x < 128);
    if (worker) {
        int p0 = blockIdx.x * 4;
        int branch = p0 >> 8;
        int o0 = p0 & 255;
        const float* m1w = branch ? q1w : w1w;
        const float* m1b = branch ? q1b : w1b;

        if (tid < BB) il_sh[tid] = 1.0f / (float)__ldg(&len[tid]);
        __syncthreads();
        // c cache: cache[b*256+d] = g_c[b*256+d] / len[b]
#pragma unroll
        for (int i = tid; i < BB * DD; i += NTHREADS)
            cache[i] = g_c[i] * il_sh[i >> 8];
        // 4 weight rows
        w_sh[tid] = m1w[(size_t)(o0 + (tid >> 8)) * DD + (tid & 255)];
        __syncthreads();

        int w = tid >> 5, lane = tid & 31;    // warp = batch
#pragma unroll
        for (int r = 0; r < 4; r++) {
            float acc = 0.0f;
#pragma unroll
            for (int k = 0; k < 8; k++)
                acc = fmaf(cache[w * 256 + lane + 32 * k], w_sh[r * 256 + lane + 32 * k], acc);
#pragma unroll
            for (int off = 16; off > 0; off >>= 1)
                acc += __shfl_down_sync(0xFFFFFFFFu, acc, off);
            if (lane == 0)
                g_h[(w * 2 + branch) * HH + o0 + r] = gelu_exact(acc + m1b[o0 + r]);
        }
    }
    grid_barrier();   // #2: g_h complete (c dead after this)

    // ---------- Phase 2b: layer 2 (CTAs 0..127); CTAs 128+ re-zero g_c ----------
    if (worker) {
        int p0 = blockIdx.x * 4;
        int branch = p0 >> 8;
        int o0 = p0 & 255;
        const float* m2w = branch ? q2w : w2w;
        const float* m2b = branch ? q2b : w2b;
        float* gout = branch ? g_bias : g_W;

        __syncthreads();   // cache reuse ordering within CTA
        // h cache for this branch: cache[b*256+d] = g_h[(b*2+branch)*256+d]
#pragma unroll
        for (int i = tid; i < BB * HH; i += NTHREADS)
            cache[i] = g_h[((i >> 8) * 2 + branch) * HH + (i & 255)];
        w_sh[tid] = m2w[(size_t)(o0 + (tid >> 8)) * HH + (tid & 255)];
        __syncthreads();

        int w = tid >> 5, lane = tid & 31;
#pragma unroll
        for (int r = 0; r < 4; r++) {
            float acc = 0.0f;
#pragma unroll
            for (int k = 0; k < 8; k++)
                acc = fmaf(cache[w * 256 + lane + 32 * k], w_sh[r * 256 + lane + 32 * k], acc);
#pragma unroll
            for (int off = 16; off > 0; off >>= 1)
                acc += __shfl_down_sync(0xFFFFFFFFu, acc, off);
            if (lane == 0)
                gout[w * DD + o0 + r] = acc + m2b[o0 + r];
        }
    } else {
        // re-zero the c accumulator for the next launch (g_c dead after barrier #2)
        for (int i = tid; i < BB * DD; i += NTHREADS) g_c[i] = 0.0f;
        __threadfence();
    }
    grid_barrier();   // #3: g_W / g_bias complete

    // ---------- Phase 3: apply (R10 verbatim: 4 load + 2 store slots, bulk I/O) ----------
    {
        const int L = __ldg(&len[b]);
        float4 wv = reinterpret_cast<const float4*>(g_W)[b * 64 + d4];
        float4 bv = reinterpret_cast<const float4*>(g_bias)[b * 64 + d4];

        for (int i = 0; i < nt; i++) {
            int ls = i % NL;
            int ss = NL + (i % NS);
            mbar_wait(mb[ls], ph[ls]); ph[ls] ^= 1;
            if (tid == 0) bulk_wait_group1();
            __syncthreads();

            int tbase = (t0 + i) * TILE_ROWS - b * TT;
            {
                int t = tbase + r2;
                float4 o = make_float4(0.f, 0.f, 0.f, 0.f);
                if (t < L) {
                    float4 xv = bufs[ls * 2048 + r2 * 64 + d4];
                    o.x = fmaf(xv.x, wv.x, xv.x);
                    o.y = fmaf(xv.y, wv.y, xv.y);
                    o.z = fmaf(xv.z, wv.z, xv.z);
                    o.w = fmaf(xv.w, wv.w, xv.w);
                    if (t == 0) { o.x += bv.x; o.y += bv.y; o.z += bv.z; o.w += bv.w; }
                }
                bufs[ss * 2048 + r2 * 64 + d4] = o;
            }
            {
                int t = tbase + r2 + 16;
                float4 o = make_float4(0.f, 0.f, 0.f, 0.f);
                if (t < L) {
                    float4 xv = bufs[ls * 2048 + (r2 + 16) * 64 + d4];
                    o.x = fmaf(xv.x, wv.x, xv.x);
                    o.y = fmaf(xv.y, wv.y, xv.y);
                    o.z = fmaf(xv.z, wv.z, xv.z);
                    o.w = fmaf(xv.w, wv.w, xv.w);
                }
                bufs[ss * 2048 + (r2 + 16) * 64 + d4] = o;
            }
            __syncthreads();
            if (tid == 0) {
                fence_proxy_async_shared();
                bulk_store(ob + (size_t)(t0 + i) * TILE_BYTES, bufa[ss], TILE_BYTES);
                bulk_commit();
                if (i + NL < nt) {
                    mbar_expect_tx(mb[ls], TILE_BYTES);
                    bulk_load(bufa[ls], xb + (size_t)(t0 + i + NL) * TILE_BYTES, TILE_BYTES, mb[ls]);
                }
            }
        }
        if (tid == 0) bulk_wait_group0();
        __syncthreads();
    }
}

// ---------------------------------------------------------------------------
extern "C" void kernel_launch(void* const* d_in, const int* in_sizes, int n_in,
                              void* d_out, int out_size) {
    const float* x     = (const float*)d_in[0];
    const int*   len_x = (const int*)d_in[1];
    const float* Ww1_w = (const float*)d_in[2];
    const float* Ww1_b = (const float*)d_in[3];
    const float* Ww2_w = (const float*)d_in[4];
    const float* Ww2_b = (const float*)d_in[5];
    const float* Wb1_w = (const float*)d_in[6];
    const float* Wb1_b = (const float*)d_in[7];
    const float* Wb2_w = (const float*)d_in[8];
    const float* Wb2_b = (const float*)d_in[9];
    float* out = (float*)d_out;

    cudaFuncSetAttribute(fused_kernel,
                         cudaFuncAttributeMaxDynamicSharedMemorySize, DYN_SMEM);
    fused_kernel<<<GRID, NTHREADS, DYN_SMEM>>>(
        x, len_x,
        Ww1_w, Ww1_b, Ww2_w, Ww2_b,
        Wb1_w, Wb1_b, Wb2_w, Wb2_b,
        out);
}